// round 12
// baseline (speedup 1.0000x reference)
#include <cuda_runtime.h>
#include <cuda_bf16.h>
#include <cstdint>

#define BB 8
#define LL 2048
#define DD 256
#define MM (BB*LL)
#define NCH 171   // ceil(LL/12)

// ---------------- scratch (device globals; no runtime allocation) ----------
__device__ __nv_bfloat16 g_xch[MM*DD], g_xcl[MM*DD];  // conv out, hi/lo planes
__device__ __nv_bfloat16 g_yh [MM*DD], g_yl [MM*DD];  // proj out (masked)
__device__ __nv_bfloat16 g_zh [MM*DD], g_zl [MM*DD];  // weighted mix
__device__ __nv_bfloat16 g_pwh[DD*DD], g_pwl[DD*DD];  // proj W hi/lo
__device__ __nv_bfloat16 g_fwh[DD*DD], g_fwl[DD*DD];  // ff W hi/lo
__device__ float g_tp[2*MM];    // per-row partial score dots (2 N-halves)
__device__ int   g_len[BB];

// ---------------- helpers ---------------------------------------------------
static __device__ __forceinline__ uint32_t su32(const void* p){
  uint32_t a;
  asm("{ .reg .u64 t; cvta.to.shared.u64 t, %1; cvt.u32.u64 %0, t; }" : "=r"(a) : "l"(p));
  return a;
}
static __device__ __forceinline__ uint32_t bfp2(float x0, float x1){
  uint32_t b0 = (uint32_t)__bfloat16_as_ushort(__float2bfloat16_rn(x0));
  uint32_t b1 = (uint32_t)__bfloat16_as_ushort(__float2bfloat16_rn(x1));
  return b0 | (b1<<16);
}
static __device__ __forceinline__ float2 unpk(uint32_t u){
  __nv_bfloat162 h = *reinterpret_cast<__nv_bfloat162*>(&u);
  return __bfloat1622float2(h);
}
static __device__ __forceinline__ void split4(const float* v, uint2& H, uint2& L){
  float h0 = __bfloat162float(__float2bfloat16_rn(v[0]));
  float h1 = __bfloat162float(__float2bfloat16_rn(v[1]));
  float h2 = __bfloat162float(__float2bfloat16_rn(v[2]));
  float h3 = __bfloat162float(__float2bfloat16_rn(v[3]));
  H = make_uint2(bfp2(h0,h1), bfp2(h2,h3));
  L = make_uint2(bfp2(v[0]-h0, v[1]-h1), bfp2(v[2]-h2, v[3]-h3));
}
static __device__ __forceinline__ void load4(const __nv_bfloat16* hi,
    const __nv_bfloat16* lo, size_t off, float* v){
  uint2 H = *(const uint2*)(hi+off);
  uint2 L = *(const uint2*)(lo+off);
  float2 a0=unpk(H.x), a1=unpk(H.y), b0=unpk(L.x), b1=unpk(L.y);
  v[0]=a0.x+b0.x; v[1]=a0.y+b0.y; v[2]=a1.x+b1.x; v[3]=a1.y+b1.y;
}
#define CP16(dst,src)  asm volatile("cp.async.ca.shared.global [%0], [%1], 16;" :: "r"(dst), "l"(src))
#define CP_COMMIT()    asm volatile("cp.async.commit_group;" ::: "memory")
#define CP_WAIT0()     asm volatile("cp.async.wait_group 0;" ::: "memory")
#define LDSM4(R, addr) asm volatile("ldmatrix.sync.aligned.m8n8.x4.shared.b16 {%0,%1,%2,%3}, [%4];" \
  : "=r"((R)[0]),"=r"((R)[1]),"=r"((R)[2]),"=r"((R)[3]) : "r"(addr))

// ---------------- K_prep: len(8) + wsplit(128) + buildxc(1024) in one grid -
#define LEN_BLKS 8
#define WS_BLKS  128
#define BX_BLKS  1024
__global__ void k_prep(const int* __restrict__ seq, const float* __restrict__ emb,
                       const float* __restrict__ cw, const float* __restrict__ cb,
                       const float* __restrict__ pw, const float* __restrict__ fw){
  int bx = blockIdx.x;
  int tid = threadIdx.x;
  if(bx < LEN_BLKS){
    __shared__ int cnt;
    if(tid==0) cnt=0;
    __syncthreads();
    int c=0;
    const int* sb = &seq[bx*LL];
    #pragma unroll
    for(int i=0;i<8;i++) c += (sb[tid + i*256] != 0);
    #pragma unroll
    for(int o=16;o>0;o>>=1) c += __shfl_xor_sync(0xffffffffu,c,o);
    if((tid&31)==0) atomicAdd(&cnt,c);
    __syncthreads();
    if(tid==0) g_len[bx]=cnt;
    return;
  }
  if(bx < LEN_BLKS + WS_BLKS){
    int i = (bx-LEN_BLKS)*256 + tid;
    int which = i >= (DD*DD/4);
    int j = which ? i - DD*DD/4 : i;
    const float* src = which ? fw : pw;
    float4 v = *(const float4*)&src[j*4];
    float f[4] = {v.x,v.y,v.z,v.w};
    uint2 H,L; split4(f,H,L);
    __nv_bfloat16* dh = which ? g_fwh : g_pwh;
    __nv_bfloat16* dl = which ? g_fwl : g_pwl;
    *(uint2*)(dh + j*4) = H;
    *(uint2*)(dl + j*4) = L;
    return;
  }
  int idx = (bx - LEN_BLKS - WS_BLKS)*256 + tid;
  int cid = idx >> 6;
  int d4  = (idx & 63) << 2;
  int m0r = cid << 2;
  int l   = m0r & (LL-1);
  float e[7][4];
  #pragma unroll
  for(int k=0;k<7;k++){
    if(l + k < LL){
      int tok = seq[m0r + k];
      float4 t = *(const float4*)&emb[tok*DD + d4];
      e[k][0]=t.x*16.f; e[k][1]=t.y*16.f; e[k][2]=t.z*16.f; e[k][3]=t.w*16.f;
    } else {
      e[k][0]=e[k][1]=e[k][2]=e[k][3]=0.f;
    }
  }
  float4 cwv[4]; float cbv[4];
  #pragma unroll
  for(int i=0;i<4;i++){ cwv[i] = *(const float4*)&cw[(d4+i)*4]; cbv[i]=cb[d4+i]; }
  #pragma unroll
  for(int j=0;j<4;j++){
    float o[4];
    #pragma unroll
    for(int i=0;i<4;i++)
      o[i] = cbv[i] + cwv[i].x*e[j][i] + cwv[i].y*e[j+1][i]
                    + cwv[i].z*e[j+2][i] + cwv[i].w*e[j+3][i];
    uint2 H,L; split4(o,H,L);
    size_t off = (size_t)(m0r+j)*DD + d4;
    *(uint2*)(g_xch+off) = H;
    *(uint2*)(g_xcl+off) = L;
  }
}

// ===== warp-MMA GEMM: 2-stage cp.async pipeline (KCH=32) + ldmatrix ========
// 3-term: Ahi*Whi + Alo*Whi + Ahi*Wlo, fp32 accum.
// schedule: wait(c) -> sync -> issue loads(c+1) -> compute(c). 1 barrier/chunk.
#define KCH 32
#define NCHK (DD/KCH)                    // 8
#define PK 40
#define PLANE_HALFS (128*PK)             // 5120
#define PLANE_B (PLANE_HALFS*2)          // 10240
#define STAGE_B (4*PLANE_B)              // 40960
#define SMEM_BYTES (2*STAGE_B + 2048)    // 83968

#define MMA_BF16(c, A0,A1,A2,A3, B0,B1) \
  asm volatile("mma.sync.aligned.m16n8k16.row.col.f32.bf16.bf16.f32 " \
    "{%0,%1,%2,%3}, {%4,%5,%6,%7}, {%8,%9}, {%0,%1,%2,%3};" \
    : "+f"((c)[0]), "+f"((c)[1]), "+f"((c)[2]), "+f"((c)[3]) \
    : "r"(A0), "r"(A1), "r"(A2), "r"(A3), "r"(B0), "r"(B1))

__global__ __launch_bounds__(256,2) void k_tgemm(
    const __nv_bfloat16* __restrict__ Ah, const __nv_bfloat16* __restrict__ Al,
    const __nv_bfloat16* __restrict__ Wh, const __nv_bfloat16* __restrict__ Wl,
    const float* __restrict__ bias, const int* __restrict__ seq,
    __nv_bfloat16* __restrict__ Ch, __nv_bfloat16* __restrict__ Cl,
    float* __restrict__ Cf, const float* __restrict__ swv, int epi)
{
  extern __shared__ __align__(16) char smraw[];
  float* t_s = (float*)(smraw + 2*STAGE_B);
  const uint32_t sbase = su32(smraw);

  const int tid = threadIdx.x;
  const int wid = tid>>5, lane = tid&31;
  const int g = lane>>2, t = lane&3;
  const int wm = wid & 1, wn = wid >> 1;
  const int m0 = blockIdx.x*128, n0 = blockIdx.y*128;

  const __nv_bfloat16* gsrc[4] = {Ah, Al, Wh, Wl};

  // ldmatrix per-lane offsets within a stage (bytes)
  const uint32_t aAoff = (((wm*64 + (lane&15))*PK) + ((lane>>4)<<3))*2;
  const uint32_t aBoff = 2*PLANE_B
      + (((wn*32 + (lane&7) + (((lane>>4)&1)<<3))*PK) + (((lane>>3)&1)<<3))*2;

  float acc[4][4][4];
  #pragma unroll
  for(int i=0;i<4;i++)
    #pragma unroll
    for(int j=0;j<4;j++)
      #pragma unroll
      for(int q=0;q<4;q++) acc[i][j][q]=0.f;

  auto load_chunk = [&](int c, int stg){
    const int k0 = c*KCH;
    #pragma unroll
    for(int u=tid; u<2048; u+=256){
      int plane = u>>9;
      int v = u & 511;
      int r = v>>2, q = v&3;
      int row0 = (plane<2) ? m0 : n0;
      const __nv_bfloat16* src = gsrc[plane] + (size_t)(row0+r)*DD + k0 + q*8;
      uint32_t dst = sbase + stg*STAGE_B + plane*PLANE_B + (r*PK + q*8)*2;
      CP16(dst, src);
    }
    CP_COMMIT();
  };

  load_chunk(0, 0);
  for(int c=0; c<NCHK; c++){
    CP_WAIT0();
    __syncthreads();                       // releases wait + protects stage reuse
    if(c+1 < NCHK) load_chunk(c+1, (c+1)&1);
    const uint32_t base = sbase + (c&1)*STAGE_B;

    #pragma unroll
    for(int ks=0; ks<2; ks++){
      const uint32_t ko = ks*32;           // 16 halves = 32 bytes
      uint32_t ah[4][4], al[4][4];
      #pragma unroll
      for(int mt=0;mt<4;mt++){
        LDSM4(ah[mt], base + aAoff + mt*(16*PK*2) + ko);
        LDSM4(al[mt], base + aAoff + PLANE_B + mt*(16*PK*2) + ko);
      }
      #pragma unroll
      for(int ntp=0;ntp<2;ntp++){
        uint32_t bh[4], bl[4];
        LDSM4(bh, base + aBoff + ntp*(16*PK*2) + ko);
        LDSM4(bl, base + aBoff + PLANE_B + ntp*(16*PK*2) + ko);
        #pragma unroll
        for(int hf=0;hf<2;hf++){
          int nt = ntp*2 + hf;
          uint32_t bh0=bh[hf*2], bh1=bh[hf*2+1];
          uint32_t bl0=bl[hf*2], bl1=bl[hf*2+1];
          #pragma unroll
          for(int mt=0;mt<4;mt++){
            MMA_BF16(acc[mt][nt], ah[mt][0],ah[mt][1],ah[mt][2],ah[mt][3], bh0,bh1);
            MMA_BF16(acc[mt][nt], al[mt][0],al[mt][1],al[mt][2],al[mt][3], bh0,bh1);
            MMA_BF16(acc[mt][nt], ah[mt][0],ah[mt][1],ah[mt][2],ah[mt][3], bl0,bl1);
          }
        }
      }
    }
  }

  // ---- epilogue ----
  if(epi==0){
    #pragma unroll
    for(int mt=0;mt<4;mt++){
      int r = wm*64 + mt*16 + g;
      int row = m0 + r;
      bool p0 = (seq[row]==0), p1 = (seq[row+8]==0);
      float s0=0.f, s1=0.f;
      #pragma unroll
      for(int nt=0;nt<4;nt++){
        int col = n0 + wn*32 + nt*8 + 2*t;
        float b0v = bias[col], b1v = bias[col+1];
        float* cc = acc[mt][nt];
        float v00 = p0 ? 0.f : cc[0]+b0v;
        float v01 = p0 ? 0.f : cc[1]+b1v;
        float v10 = p1 ? 0.f : cc[2]+b0v;
        float v11 = p1 ? 0.f : cc[3]+b1v;
        float w0 = swv[col], w1 = swv[col+1];
        s0 += v00*w0 + v01*w1;
        s1 += v10*w0 + v11*w1;
        float h0 = __bfloat162float(__float2bfloat16_rn(v00));
        float h1 = __bfloat162float(__float2bfloat16_rn(v01));
        *(uint32_t*)(Ch + (size_t)row*DD + col) = bfp2(h0,h1);
        *(uint32_t*)(Cl + (size_t)row*DD + col) = bfp2(v00-h0, v01-h1);
        float h2 = __bfloat162float(__float2bfloat16_rn(v10));
        float h3 = __bfloat162float(__float2bfloat16_rn(v11));
        *(uint32_t*)(Ch + (size_t)(row+8)*DD + col) = bfp2(h2,h3);
        *(uint32_t*)(Cl + (size_t)(row+8)*DD + col) = bfp2(v10-h2, v11-h3);
      }
      s0 += __shfl_xor_sync(0xffffffffu, s0, 1);
      s0 += __shfl_xor_sync(0xffffffffu, s0, 2);
      s1 += __shfl_xor_sync(0xffffffffu, s1, 1);
      s1 += __shfl_xor_sync(0xffffffffu, s1, 2);
      if(t==0){
        t_s[wn*128 + r]     = s0;
        t_s[wn*128 + r + 8] = s1;
      }
    }
    __syncthreads();
    if(tid < 128){
      float v = t_s[tid] + t_s[128+tid] + t_s[256+tid] + t_s[384+tid];
      g_tp[blockIdx.y*MM + m0 + tid] = v;
    }
  } else {
    #pragma unroll
    for(int mt=0;mt<4;mt++){
      int row = m0 + wm*64 + mt*16 + g;
      #pragma unroll
      for(int nt=0;nt<4;nt++){
        int col = n0 + wn*32 + nt*8 + 2*t;
        float b0v = bias[col], b1v = bias[col+1];
        float* cc = acc[mt][nt];
        size_t o0off = (size_t)row*DD + col;
        size_t o1off = (size_t)(row+8)*DD + col;
        float2 zh0 = unpk(*(const uint32_t*)(Ah + o0off));
        float2 zl0 = unpk(*(const uint32_t*)(Al + o0off));
        float2 zh1 = unpk(*(const uint32_t*)(Ah + o1off));
        float2 zl1 = unpk(*(const uint32_t*)(Al + o1off));
        float2 o0 = make_float2((zh0.x+zl0.x) + fmaxf(cc[0]+b0v,0.f),
                                (zh0.y+zl0.y) + fmaxf(cc[1]+b1v,0.f));
        float2 o1 = make_float2((zh1.x+zl1.x) + fmaxf(cc[2]+b0v,0.f),
                                (zh1.y+zl1.y) + fmaxf(cc[3]+b1v,0.f));
        *(float2*)&Cf[o0off] = o0;
        *(float2*)&Cf[o1off] = o1;
      }
    }
  }
}

// ------- K_mixw: fused collapsed-softmax weights + mix, 12 rows/thread -----
__global__ __launch_bounds__(256) void k_mixw(){
  __shared__ float4 wsm[48];
  int tid = threadIdx.x;
  int cid0 = blockIdx.x*4;
  if(tid < 48){
    int s = tid;
    int cid = cid0 + s/12, j = s - (s/12)*12;
    int b = cid/NCH, c = cid - b*NCH;
    int l0 = c*12, l = l0 + j;
    int len = g_len[b];
    float4 w = make_float4(0.f,0.f,0.f,0.f);
    if(l < LL && l < len){
      const float* t0p = &g_tp[b*LL];
      const float* t1p = &g_tp[MM + b*LL];
      float tv[12];
      #pragma unroll
      for(int jj=0;jj<12;jj++){
        int p = l0 + jj;
        tv[jj] = (p < LL) ? (t0p[p] + t1p[p]) : 0.f;
      }
      int a2 = j & ~1, a3 = (j/3)*3, a4 = j & ~3;
      float s2v = tv[a2]+tv[a2+1];
      float s3v = tv[a3]+tv[a3+1]+tv[a3+2];
      float s4v = tv[a4]+tv[a4+1]+tv[a4+2]+tv[a4+3];
      float c2 = (float)(min(l0+a2+2, len) - (l0+a2));
      float c3 = (float)(min(l0+a3+3, len) - (l0+a3));
      float c4 = (float)(min(l0+a4+4, len) - (l0+a4));
      float m2 = s2v/c2, m3 = s3v/c3, m4 = s4v/c4;
      float t0 = tv[j];
      float mx = fmaxf(fmaxf(t0,m2), fmaxf(m3,m4));
      float e0=expf(t0-mx), e2=expf(m2-mx), e3=expf(m3-mx), e4=expf(m4-mx);
      float inv = 1.f/(e0 + 2.f*e2 + 3.f*e3 + 4.f*e4);
      w = make_float4(e0*inv, 2.f*e2*inv/c2, 3.f*e3*inv/c3, 4.f*e4*inv/c4);
    }
    wsm[s] = w;
  }
  __syncthreads();

  int idx = blockIdx.x*256 + tid;
  int cid = idx >> 6;
  int d4  = (idx & 63) << 2;
  int b = cid / NCH, c = cid - b*NCH;
  int l0 = c*12;
  int slot0 = (tid>>6)*12;
  size_t base = ((size_t)b*LL)*DD + d4;
  float v[12][4];
  float s2[6][4], s3[4][4];
  #pragma unroll
  for(int j=0;j<6;j++) s2[j][0]=s2[j][1]=s2[j][2]=s2[j][3]=0.f;
  #pragma unroll
  for(int j=0;j<4;j++) s3[j][0]=s3[j][1]=s3[j][2]=s3[j][3]=0.f;
  #pragma unroll
  for(int j=0;j<12;j++){
    int l = l0 + j;
    if(l < LL){
      load4(g_yh, g_yl, base + (size_t)l*DD, v[j]);
      #pragma unroll
      for(int i=0;i<4;i++){
        s2[j>>1][i] += v[j][i];
        s3[j/3][i]  += v[j][i];
      }
    } else {
      v[j][0]=v[j][1]=v[j][2]=v[j][3]=0.f;
    }
  }
  #pragma unroll
  for(int j=0;j<12;j++){
    int l = l0 + j;
    if(l < LL){
      size_t off = base + (size_t)l*DD;
      float4 w = wsm[slot0 + j];
      int q = j>>2;
      float o[4];
      #pragma unroll
      for(int i=0;i<4;i++)
        o[i] = w.x*v[j][i] + w.y*s2[j>>1][i] + w.z*s3[j/3][i]
             + w.w*(s2[2*q][i] + s2[2*q+1][i]);
      uint2 H,L; split4(o,H,L);
      *(uint2*)(g_zh+off) = H;
      *(uint2*)(g_zl+off) = L;
    }
  }
}

// ---------------- launch ----------------------------------------------------
extern "C" void kernel_launch(void* const* d_in, const int* in_sizes, int n_in,
                              void* d_out, int out_size){
  const int*   seq = (const int*)  d_in[0];
  const float* emb = (const float*)d_in[2];
  const float* cw  = (const float*)d_in[3];
  const float* cb  = (const float*)d_in[4];
  const float* pw  = (const float*)d_in[5];
  const float* pb  = (const float*)d_in[6];
  const float* sw  = (const float*)d_in[7];
  const float* fw  = (const float*)d_in[9];
  const float* fb  = (const float*)d_in[10];
  float* out = (float*)d_out;

  __nv_bfloat16 *xch,*xcl,*yh,*yl,*zh,*zl,*pwh,*pwl,*fwh,*fwl;
  cudaGetSymbolAddress((void**)&xch, g_xch);
  cudaGetSymbolAddress((void**)&xcl, g_xcl);
  cudaGetSymbolAddress((void**)&yh,  g_yh);
  cudaGetSymbolAddress((void**)&yl,  g_yl);
  cudaGetSymbolAddress((void**)&zh,  g_zh);
  cudaGetSymbolAddress((void**)&zl,  g_zl);
  cudaGetSymbolAddress((void**)&pwh, g_pwh);
  cudaGetSymbolAddress((void**)&pwl, g_pwl);
  cudaGetSymbolAddress((void**)&fwh, g_fwh);
  cudaGetSymbolAddress((void**)&fwl, g_fwl);

  cudaFuncSetAttribute(k_tgemm, cudaFuncAttributeMaxDynamicSharedMemorySize, SMEM_BYTES);

  k_prep <<<LEN_BLKS+WS_BLKS+BX_BLKS, 256>>>(seq, emb, cw, cb, pw, fw);
  k_tgemm<<<dim3(MM/128, 2), 256, SMEM_BYTES>>>(xch, xcl, pwh, pwl, pb, seq, yh, yl, nullptr, sw, 0);
  k_mixw <<<BB*NCH*64/256, 256>>>();
  k_tgemm<<<dim3(MM/128, 2), 256, SMEM_BYTES>>>(zh, zl, fwh, fwl, fb, seq, nullptr, nullptr, out, sw, 1);
}

// round 13
// speedup vs baseline: 1.0264x; 1.0264x over previous
#include <cuda_runtime.h>
#include <cuda_bf16.h>
#include <cstdint>

#define BB 8
#define LL 2048
#define DD 256
#define MM (BB*LL)
#define NCH 171   // ceil(LL/12)

// ---------------- scratch (device globals; no runtime allocation) ----------
__device__ __nv_bfloat16 g_xch[MM*DD], g_xcl[MM*DD];  // conv out, hi/lo planes
__device__ __nv_bfloat16 g_yh [MM*DD], g_yl [MM*DD];  // proj out (masked)
__device__ __nv_bfloat16 g_zh [MM*DD], g_zl [MM*DD];  // weighted mix
__device__ __nv_bfloat16 g_pwh[DD*DD], g_pwl[DD*DD];  // proj W hi/lo
__device__ __nv_bfloat16 g_fwh[DD*DD], g_fwl[DD*DD];  // ff W hi/lo
__device__ float g_tp[2*MM];    // per-row partial score dots (2 N-halves)
__device__ int   g_len[BB];

// ---------------- helpers ---------------------------------------------------
static __device__ __forceinline__ uint32_t su32(const void* p){
  uint32_t a;
  asm("{ .reg .u64 t; cvta.to.shared.u64 t, %1; cvt.u32.u64 %0, t; }" : "=r"(a) : "l"(p));
  return a;
}
static __device__ __forceinline__ uint32_t bfp2(float x0, float x1){
  uint32_t b0 = (uint32_t)__bfloat16_as_ushort(__float2bfloat16_rn(x0));
  uint32_t b1 = (uint32_t)__bfloat16_as_ushort(__float2bfloat16_rn(x1));
  return b0 | (b1<<16);
}
static __device__ __forceinline__ float2 unpk(uint32_t u){
  __nv_bfloat162 h = *reinterpret_cast<__nv_bfloat162*>(&u);
  return __bfloat1622float2(h);
}
static __device__ __forceinline__ void split4(const float* v, uint2& H, uint2& L){
  float h0 = __bfloat162float(__float2bfloat16_rn(v[0]));
  float h1 = __bfloat162float(__float2bfloat16_rn(v[1]));
  float h2 = __bfloat162float(__float2bfloat16_rn(v[2]));
  float h3 = __bfloat162float(__float2bfloat16_rn(v[3]));
  H = make_uint2(bfp2(h0,h1), bfp2(h2,h3));
  L = make_uint2(bfp2(v[0]-h0, v[1]-h1), bfp2(v[2]-h2, v[3]-h3));
}
static __device__ __forceinline__ void load4(const __nv_bfloat16* hi,
    const __nv_bfloat16* lo, size_t off, float* v){
  uint2 H = *(const uint2*)(hi+off);
  uint2 L = *(const uint2*)(lo+off);
  float2 a0=unpk(H.x), a1=unpk(H.y), b0=unpk(L.x), b1=unpk(L.y);
  v[0]=a0.x+b0.x; v[1]=a0.y+b0.y; v[2]=a1.x+b1.x; v[3]=a1.y+b1.y;
}
// .cg = L2-only (bypass L1): tile data is single-use; keep L1tex free for LDSM
#define CP16(dst,src)  asm volatile("cp.async.cg.shared.global [%0], [%1], 16;" :: "r"(dst), "l"(src))
#define CP_COMMIT()    asm volatile("cp.async.commit_group;" ::: "memory")
#define CP_WAIT0()     asm volatile("cp.async.wait_group 0;" ::: "memory")
#define LDSM4(R, addr) asm volatile("ldmatrix.sync.aligned.m8n8.x4.shared.b16 {%0,%1,%2,%3}, [%4];" \
  : "=r"((R)[0]),"=r"((R)[1]),"=r"((R)[2]),"=r"((R)[3]) : "r"(addr))

// ---------------- K_prep: len(8) + wsplit(128) + buildxc(1024) in one grid -
#define LEN_BLKS 8
#define WS_BLKS  128
#define BX_BLKS  1024
__global__ void k_prep(const int* __restrict__ seq, const float* __restrict__ emb,
                       const float* __restrict__ cw, const float* __restrict__ cb,
                       const float* __restrict__ pw, const float* __restrict__ fw){
  int bx = blockIdx.x;
  int tid = threadIdx.x;
  if(bx < LEN_BLKS){
    __shared__ int cnt;
    if(tid==0) cnt=0;
    __syncthreads();
    int c=0;
    const int* sb = &seq[bx*LL];
    #pragma unroll
    for(int i=0;i<8;i++) c += (sb[tid + i*256] != 0);
    #pragma unroll
    for(int o=16;o>0;o>>=1) c += __shfl_xor_sync(0xffffffffu,c,o);
    if((tid&31)==0) atomicAdd(&cnt,c);
    __syncthreads();
    if(tid==0) g_len[bx]=cnt;
    return;
  }
  if(bx < LEN_BLKS + WS_BLKS){
    int i = (bx-LEN_BLKS)*256 + tid;
    int which = i >= (DD*DD/4);
    int j = which ? i - DD*DD/4 : i;
    const float* src = which ? fw : pw;
    float4 v = *(const float4*)&src[j*4];
    float f[4] = {v.x,v.y,v.z,v.w};
    uint2 H,L; split4(f,H,L);
    __nv_bfloat16* dh = which ? g_fwh : g_pwh;
    __nv_bfloat16* dl = which ? g_fwl : g_pwl;
    *(uint2*)(dh + j*4) = H;
    *(uint2*)(dl + j*4) = L;
    return;
  }
  int idx = (bx - LEN_BLKS - WS_BLKS)*256 + tid;
  int cid = idx >> 6;
  int d4  = (idx & 63) << 2;
  int m0r = cid << 2;
  int l   = m0r & (LL-1);
  float e[7][4];
  #pragma unroll
  for(int k=0;k<7;k++){
    if(l + k < LL){
      int tok = seq[m0r + k];
      float4 t = *(const float4*)&emb[tok*DD + d4];
      e[k][0]=t.x*16.f; e[k][1]=t.y*16.f; e[k][2]=t.z*16.f; e[k][3]=t.w*16.f;
    } else {
      e[k][0]=e[k][1]=e[k][2]=e[k][3]=0.f;
    }
  }
  float4 cwv[4]; float cbv[4];
  #pragma unroll
  for(int i=0;i<4;i++){ cwv[i] = *(const float4*)&cw[(d4+i)*4]; cbv[i]=cb[d4+i]; }
  #pragma unroll
  for(int j=0;j<4;j++){
    float o[4];
    #pragma unroll
    for(int i=0;i<4;i++)
      o[i] = cbv[i] + cwv[i].x*e[j][i] + cwv[i].y*e[j+1][i]
                    + cwv[i].z*e[j+2][i] + cwv[i].w*e[j+3][i];
    uint2 H,L; split4(o,H,L);
    size_t off = (size_t)(m0r+j)*DD + d4;
    *(uint2*)(g_xch+off) = H;
    *(uint2*)(g_xcl+off) = L;
  }
}

// ============== warp-MMA GEMM (KCH=64, single stage, ldmatrix frags) =======
// 3-term: Ahi*Whi + Alo*Whi + Ahi*Wlo, fp32 accum.
#define PK 72
#define TILE_HALFS (128*PK)
#define PLANE_B (TILE_HALFS*2)                // bytes per plane
#define SMEM_BYTES (4*PLANE_B + 2048)

#define MMA_BF16(c, A0,A1,A2,A3, B0,B1) \
  asm volatile("mma.sync.aligned.m16n8k16.row.col.f32.bf16.bf16.f32 " \
    "{%0,%1,%2,%3}, {%4,%5,%6,%7}, {%8,%9}, {%0,%1,%2,%3};" \
    : "+f"((c)[0]), "+f"((c)[1]), "+f"((c)[2]), "+f"((c)[3]) \
    : "r"(A0), "r"(A1), "r"(A2), "r"(A3), "r"(B0), "r"(B1))

__global__ __launch_bounds__(256,2) void k_tgemm(
    const __nv_bfloat16* __restrict__ Ah, const __nv_bfloat16* __restrict__ Al,
    const __nv_bfloat16* __restrict__ Wh, const __nv_bfloat16* __restrict__ Wl,
    const float* __restrict__ bias, const int* __restrict__ seq,
    __nv_bfloat16* __restrict__ Ch, __nv_bfloat16* __restrict__ Cl,
    float* __restrict__ Cf, const float* __restrict__ swv, int epi)
{
  extern __shared__ __align__(16) char smraw[];
  float* t_s = (float*)(smraw + 4*PLANE_B);
  const uint32_t sbase = su32(smraw);

  const int tid = threadIdx.x;
  const int wid = tid>>5, lane = tid&31;
  const int g = lane>>2, t = lane&3;
  const int wm = wid & 1, wn = wid >> 1;
  const int m0 = blockIdx.x*128, n0 = blockIdx.y*128;

  const __nv_bfloat16* gsrc[4] = {Ah, Al, Wh, Wl};

  // ldmatrix per-lane source addresses
  const uint32_t aA = sbase + (((wm*64 + (lane&15))*PK) + ((lane>>4)<<3))*2;
  const uint32_t aB = sbase + 2*PLANE_B
      + (((wn*32 + (lane&7) + (((lane>>4)&1)<<3))*PK) + (((lane>>3)&1)<<3))*2;

  float acc[4][4][4];
  #pragma unroll
  for(int i=0;i<4;i++)
    #pragma unroll
    for(int j=0;j<4;j++)
      #pragma unroll
      for(int q=0;q<4;q++) acc[i][j][q]=0.f;

  for(int c4=0;c4<4;c4++){
    const int k0 = c4*64;
    if(c4) __syncthreads();
    #pragma unroll
    for(int u=tid; u<4096; u+=256){
      int plane = u>>10;
      int v = u & 1023;
      int r = v>>3, q = v&7;
      int row0 = (plane<2) ? m0 : n0;
      const __nv_bfloat16* src = gsrc[plane] + (size_t)(row0+r)*DD + k0 + q*8;
      uint32_t dst = sbase + (plane*TILE_HALFS + r*PK + q*8)*2;
      CP16(dst, src);
    }
    CP_COMMIT(); CP_WAIT0();
    __syncthreads();

    #pragma unroll
    for(int ks=0; ks<4; ks++){
      const uint32_t ko = ks*32;               // 16 halves = 32 bytes
      uint32_t ah[4][4], al[4][4];
      #pragma unroll
      for(int mt=0;mt<4;mt++){
        LDSM4(ah[mt], aA + mt*(16*PK*2) + ko);
        LDSM4(al[mt], aA + PLANE_B + mt*(16*PK*2) + ko);
      }
      #pragma unroll
      for(int ntp=0;ntp<2;ntp++){
        uint32_t bh[4], bl[4];
        LDSM4(bh, aB + ntp*(16*PK*2) + ko);
        LDSM4(bl, aB + PLANE_B + ntp*(16*PK*2) + ko);
        #pragma unroll
        for(int hf=0;hf<2;hf++){
          int nt = ntp*2 + hf;
          uint32_t bh0=bh[hf*2], bh1=bh[hf*2+1];
          uint32_t bl0=bl[hf*2], bl1=bl[hf*2+1];
          #pragma unroll
          for(int mt=0;mt<4;mt++){
            MMA_BF16(acc[mt][nt], ah[mt][0],ah[mt][1],ah[mt][2],ah[mt][3], bh0,bh1);
            MMA_BF16(acc[mt][nt], al[mt][0],al[mt][1],al[mt][2],al[mt][3], bh0,bh1);
            MMA_BF16(acc[mt][nt], ah[mt][0],ah[mt][1],ah[mt][2],ah[mt][3], bl0,bl1);
          }
        }
      }
    }
  }

  // ---- epilogue ----
  if(epi==0){
    #pragma unroll
    for(int mt=0;mt<4;mt++){
      int r = wm*64 + mt*16 + g;
      int row = m0 + r;
      bool p0 = (seq[row]==0), p1 = (seq[row+8]==0);
      float s0=0.f, s1=0.f;
      #pragma unroll
      for(int nt=0;nt<4;nt++){
        int col = n0 + wn*32 + nt*8 + 2*t;
        float b0v = bias[col], b1v = bias[col+1];
        float* cc = acc[mt][nt];
        float v00 = p0 ? 0.f : cc[0]+b0v;
        float v01 = p0 ? 0.f : cc[1]+b1v;
        float v10 = p1 ? 0.f : cc[2]+b0v;
        float v11 = p1 ? 0.f : cc[3]+b1v;
        float w0 = swv[col], w1 = swv[col+1];
        s0 += v00*w0 + v01*w1;
        s1 += v10*w0 + v11*w1;
        float h0 = __bfloat162float(__float2bfloat16_rn(v00));
        float h1 = __bfloat162float(__float2bfloat16_rn(v01));
        *(uint32_t*)(Ch + (size_t)row*DD + col) = bfp2(h0,h1);
        *(uint32_t*)(Cl + (size_t)row*DD + col) = bfp2(v00-h0, v01-h1);
        float h2 = __bfloat162float(__float2bfloat16_rn(v10));
        float h3 = __bfloat162float(__float2bfloat16_rn(v11));
        *(uint32_t*)(Ch + (size_t)(row+8)*DD + col) = bfp2(h2,h3);
        *(uint32_t*)(Cl + (size_t)(row+8)*DD + col) = bfp2(v10-h2, v11-h3);
      }
      s0 += __shfl_xor_sync(0xffffffffu, s0, 1);
      s0 += __shfl_xor_sync(0xffffffffu, s0, 2);
      s1 += __shfl_xor_sync(0xffffffffu, s1, 1);
      s1 += __shfl_xor_sync(0xffffffffu, s1, 2);
      if(t==0){
        t_s[wn*128 + r]     = s0;
        t_s[wn*128 + r + 8] = s1;
      }
    }
    __syncthreads();
    if(tid < 128){
      float v = t_s[tid] + t_s[128+tid] + t_s[256+tid] + t_s[384+tid];
      g_tp[blockIdx.y*MM + m0 + tid] = v;
    }
  } else {
    #pragma unroll
    for(int mt=0;mt<4;mt++){
      int row = m0 + wm*64 + mt*16 + g;
      #pragma unroll
      for(int nt=0;nt<4;nt++){
        int col = n0 + wn*32 + nt*8 + 2*t;
        float b0v = bias[col], b1v = bias[col+1];
        float* cc = acc[mt][nt];
        size_t o0off = (size_t)row*DD + col;
        size_t o1off = (size_t)(row+8)*DD + col;
        float2 zh0 = unpk(*(const uint32_t*)(Ah + o0off));
        float2 zl0 = unpk(*(const uint32_t*)(Al + o0off));
        float2 zh1 = unpk(*(const uint32_t*)(Ah + o1off));
        float2 zl1 = unpk(*(const uint32_t*)(Al + o1off));
        float2 o0 = make_float2((zh0.x+zl0.x) + fmaxf(cc[0]+b0v,0.f),
                                (zh0.y+zl0.y) + fmaxf(cc[1]+b1v,0.f));
        float2 o1 = make_float2((zh1.x+zl1.x) + fmaxf(cc[2]+b0v,0.f),
                                (zh1.y+zl1.y) + fmaxf(cc[3]+b1v,0.f));
        *(float2*)&Cf[o0off] = o0;
        *(float2*)&Cf[o1off] = o1;
      }
    }
  }
}

// ------- K_mixw: fused collapsed-softmax weights + mix, 12 rows/thread -----
__global__ __launch_bounds__(256) void k_mixw(){
  __shared__ float4 wsm[48];
  int tid = threadIdx.x;
  int cid0 = blockIdx.x*4;
  if(tid < 48){
    int s = tid;
    int cid = cid0 + s/12, j = s - (s/12)*12;
    int b = cid/NCH, c = cid - b*NCH;
    int l0 = c*12, l = l0 + j;
    int len = g_len[b];
    float4 w = make_float4(0.f,0.f,0.f,0.f);
    if(l < LL && l < len){
      const float* t0p = &g_tp[b*LL];
      const float* t1p = &g_tp[MM + b*LL];
      float tv[12];
      #pragma unroll
      for(int jj=0;jj<12;jj++){
        int p = l0 + jj;
        tv[jj] = (p < LL) ? (t0p[p] + t1p[p]) : 0.f;
      }
      int a2 = j & ~1, a3 = (j/3)*3, a4 = j & ~3;
      float s2v = tv[a2]+tv[a2+1];
      float s3v = tv[a3]+tv[a3+1]+tv[a3+2];
      float s4v = tv[a4]+tv[a4+1]+tv[a4+2]+tv[a4+3];
      float c2 = (float)(min(l0+a2+2, len) - (l0+a2));
      float c3 = (float)(min(l0+a3+3, len) - (l0+a3));
      float c4 = (float)(min(l0+a4+4, len) - (l0+a4));
      float m2 = s2v/c2, m3 = s3v/c3, m4 = s4v/c4;
      float t0 = tv[j];
      float mx = fmaxf(fmaxf(t0,m2), fmaxf(m3,m4));
      float e0=expf(t0-mx), e2=expf(m2-mx), e3=expf(m3-mx), e4=expf(m4-mx);
      float inv = 1.f/(e0 + 2.f*e2 + 3.f*e3 + 4.f*e4);
      w = make_float4(e0*inv, 2.f*e2*inv/c2, 3.f*e3*inv/c3, 4.f*e4*inv/c4);
    }
    wsm[s] = w;
  }
  __syncthreads();

  int idx = blockIdx.x*256 + tid;
  int cid = idx >> 6;
  int d4  = (idx & 63) << 2;
  int b = cid / NCH, c = cid - b*NCH;
  int l0 = c*12;
  int slot0 = (tid>>6)*12;
  size_t base = ((size_t)b*LL)*DD + d4;
  float v[12][4];
  float s2[6][4], s3[4][4];
  #pragma unroll
  for(int j=0;j<6;j++) s2[j][0]=s2[j][1]=s2[j][2]=s2[j][3]=0.f;
  #pragma unroll
  for(int j=0;j<4;j++) s3[j][0]=s3[j][1]=s3[j][2]=s3[j][3]=0.f;
  #pragma unroll
  for(int j=0;j<12;j++){
    int l = l0 + j;
    if(l < LL){
      load4(g_yh, g_yl, base + (size_t)l*DD, v[j]);
      #pragma unroll
      for(int i=0;i<4;i++){
        s2[j>>1][i] += v[j][i];
        s3[j/3][i]  += v[j][i];
      }
    } else {
      v[j][0]=v[j][1]=v[j][2]=v[j][3]=0.f;
    }
  }
  #pragma unroll
  for(int j=0;j<12;j++){
    int l = l0 + j;
    if(l < LL){
      size_t off = base + (size_t)l*DD;
      float4 w = wsm[slot0 + j];
      int q = j>>2;
      float o[4];
      #pragma unroll
      for(int i=0;i<4;i++)
        o[i] = w.x*v[j][i] + w.y*s2[j>>1][i] + w.z*s3[j/3][i]
             + w.w*(s2[2*q][i] + s2[2*q+1][i]);
      uint2 H,L; split4(o,H,L);
      *(uint2*)(g_zh+off) = H;
      *(uint2*)(g_zl+off) = L;
    }
  }
}

// ---------------- launch ----------------------------------------------------
extern "C" void kernel_launch(void* const* d_in, const int* in_sizes, int n_in,
                              void* d_out, int out_size){
  const int*   seq = (const int*)  d_in[0];
  const float* emb = (const float*)d_in[2];
  const float* cw  = (const float*)d_in[3];
  const float* cb  = (const float*)d_in[4];
  const float* pw  = (const float*)d_in[5];
  const float* pb  = (const float*)d_in[6];
  const float* sw  = (const float*)d_in[7];
  const float* fw  = (const float*)d_in[9];
  const float* fb  = (const float*)d_in[10];
  float* out = (float*)d_out;

  __nv_bfloat16 *xch,*xcl,*yh,*yl,*zh,*zl,*pwh,*pwl,*fwh,*fwl;
  cudaGetSymbolAddress((void**)&xch, g_xch);
  cudaGetSymbolAddress((void**)&xcl, g_xcl);
  cudaGetSymbolAddress((void**)&yh,  g_yh);
  cudaGetSymbolAddress((void**)&yl,  g_yl);
  cudaGetSymbolAddress((void**)&zh,  g_zh);
  cudaGetSymbolAddress((void**)&zl,  g_zl);
  cudaGetSymbolAddress((void**)&pwh, g_pwh);
  cudaGetSymbolAddress((void**)&pwl, g_pwl);
  cudaGetSymbolAddress((void**)&fwh, g_fwh);
  cudaGetSymbolAddress((void**)&fwl, g_fwl);

  cudaFuncSetAttribute(k_tgemm, cudaFuncAttributeMaxDynamicSharedMemorySize, SMEM_BYTES);

  k_prep <<<LEN_BLKS+WS_BLKS+BX_BLKS, 256>>>(seq, emb, cw, cb, pw, fw);
  k_tgemm<<<dim3(MM/128, 2), 256, SMEM_BYTES>>>(xch, xcl, pwh, pwl, pb, seq, yh, yl, nullptr, sw, 0);
  k_mixw <<<BB*NCH*64/256, 256>>>();
  k_tgemm<<<dim3(MM/128, 2), 256, SMEM_BYTES>>>(zh, zl, fwh, fwl, fb, seq, nullptr, nullptr, out, sw, 1);
}

// round 14
// speedup vs baseline: 1.0702x; 1.0426x over previous
#include <cuda_runtime.h>
#include <cuda_bf16.h>
#include <cstdint>

#define BB 8
#define LL 2048
#define DD 256
#define MM (BB*LL)
#define NCH 171   // ceil(LL/12)

// ---------------- scratch (device globals; no runtime allocation) ----------
__device__ __nv_bfloat16 g_xch[MM*DD], g_xcl[MM*DD];  // conv out, hi/lo planes
__device__ __nv_bfloat16 g_yh [MM*DD], g_yl [MM*DD];  // proj out (masked)
__device__ __nv_bfloat16 g_zh [MM*DD], g_zl [MM*DD];  // weighted mix
__device__ __nv_bfloat16 g_pwh[DD*DD], g_pwl[DD*DD];  // proj W hi/lo
__device__ __nv_bfloat16 g_fwh[DD*DD], g_fwl[DD*DD];  // ff W hi/lo
__device__ float g_tp[2*MM];    // per-row partial score dots (2 N-halves)
__device__ int   g_len[BB];

// ---------------- helpers ---------------------------------------------------
static __device__ __forceinline__ uint32_t su32(const void* p){
  uint32_t a;
  asm("{ .reg .u64 t; cvta.to.shared.u64 t, %1; cvt.u32.u64 %0, t; }" : "=r"(a) : "l"(p));
  return a;
}
static __device__ __forceinline__ uint32_t bfp2(float x0, float x1){
  uint32_t b0 = (uint32_t)__bfloat16_as_ushort(__float2bfloat16_rn(x0));
  uint32_t b1 = (uint32_t)__bfloat16_as_ushort(__float2bfloat16_rn(x1));
  return b0 | (b1<<16);
}
static __device__ __forceinline__ float2 unpk(uint32_t u){
  __nv_bfloat162 h = *reinterpret_cast<__nv_bfloat162*>(&u);
  return __bfloat1622float2(h);
}
static __device__ __forceinline__ void split4(const float* v, uint2& H, uint2& L){
  float h0 = __bfloat162float(__float2bfloat16_rn(v[0]));
  float h1 = __bfloat162float(__float2bfloat16_rn(v[1]));
  float h2 = __bfloat162float(__float2bfloat16_rn(v[2]));
  float h3 = __bfloat162float(__float2bfloat16_rn(v[3]));
  H = make_uint2(bfp2(h0,h1), bfp2(h2,h3));
  L = make_uint2(bfp2(v[0]-h0, v[1]-h1), bfp2(v[2]-h2, v[3]-h3));
}
static __device__ __forceinline__ void load4(const __nv_bfloat16* hi,
    const __nv_bfloat16* lo, size_t off, float* v){
  uint2 H = *(const uint2*)(hi+off);
  uint2 L = *(const uint2*)(lo+off);
  float2 a0=unpk(H.x), a1=unpk(H.y), b0=unpk(L.x), b1=unpk(L.y);
  v[0]=a0.x+b0.x; v[1]=a0.y+b0.y; v[2]=a1.x+b1.x; v[3]=a1.y+b1.y;
}
#define CP16(dst,src)  asm volatile("cp.async.ca.shared.global [%0], [%1], 16;" :: "r"(dst), "l"(src))
#define CP_COMMIT()    asm volatile("cp.async.commit_group;" ::: "memory")
#define CP_WAIT0()     asm volatile("cp.async.wait_group 0;" ::: "memory")
#define LDSM4(R, addr) asm volatile("ldmatrix.sync.aligned.m8n8.x4.shared.b16 {%0,%1,%2,%3}, [%4];" \
  : "=r"((R)[0]),"=r"((R)[1]),"=r"((R)[2]),"=r"((R)[3]) : "r"(addr))

// ---------------- K_prep: len(8) + wsplit(128) + buildxc(1024) in one grid -
#define LEN_BLKS 8
#define WS_BLKS  128
#define BX_BLKS  1024
__global__ void k_prep(const int* __restrict__ seq, const float* __restrict__ emb,
                       const float* __restrict__ cw, const float* __restrict__ cb,
                       const float* __restrict__ pw, const float* __restrict__ fw){
  int bx = blockIdx.x;
  int tid = threadIdx.x;
  if(bx < LEN_BLKS){
    __shared__ int cnt;
    if(tid==0) cnt=0;
    __syncthreads();
    int c=0;
    const int* sb = &seq[bx*LL];
    #pragma unroll
    for(int i=0;i<8;i++) c += (sb[tid + i*256] != 0);
    #pragma unroll
    for(int o=16;o>0;o>>=1) c += __shfl_xor_sync(0xffffffffu,c,o);
    if((tid&31)==0) atomicAdd(&cnt,c);
    __syncthreads();
    if(tid==0) g_len[bx]=cnt;
    return;
  }
  if(bx < LEN_BLKS + WS_BLKS){
    int i = (bx-LEN_BLKS)*256 + tid;
    int which = i >= (DD*DD/4);
    int j = which ? i - DD*DD/4 : i;
    const float* src = which ? fw : pw;
    float4 v = *(const float4*)&src[j*4];
    float f[4] = {v.x,v.y,v.z,v.w};
    uint2 H,L; split4(f,H,L);
    __nv_bfloat16* dh = which ? g_fwh : g_pwh;
    __nv_bfloat16* dl = which ? g_fwl : g_pwl;
    *(uint2*)(dh + j*4) = H;
    *(uint2*)(dl + j*4) = L;
    return;
  }
  int idx = (bx - LEN_BLKS - WS_BLKS)*256 + tid;
  int cid = idx >> 6;
  int d4  = (idx & 63) << 2;
  int m0r = cid << 2;
  int l   = m0r & (LL-1);
  float e[7][4];
  #pragma unroll
  for(int k=0;k<7;k++){
    if(l + k < LL){
      int tok = seq[m0r + k];
      float4 t = *(const float4*)&emb[tok*DD + d4];
      e[k][0]=t.x*16.f; e[k][1]=t.y*16.f; e[k][2]=t.z*16.f; e[k][3]=t.w*16.f;
    } else {
      e[k][0]=e[k][1]=e[k][2]=e[k][3]=0.f;
    }
  }
  float4 cwv[4]; float cbv[4];
  #pragma unroll
  for(int i=0;i<4;i++){ cwv[i] = *(const float4*)&cw[(d4+i)*4]; cbv[i]=cb[d4+i]; }
  #pragma unroll
  for(int j=0;j<4;j++){
    float o[4];
    #pragma unroll
    for(int i=0;i<4;i++)
      o[i] = cbv[i] + cwv[i].x*e[j][i] + cwv[i].y*e[j+1][i]
                    + cwv[i].z*e[j+2][i] + cwv[i].w*e[j+3][i];
    uint2 H,L; split4(o,H,L);
    size_t off = (size_t)(m0r+j)*DD + d4;
    *(uint2*)(g_xch+off) = H;
    *(uint2*)(g_xcl+off) = L;
  }
}

// ============== warp-MMA GEMM (KCH=64, ldmatrix, interleaved terms) ========
// 3-term: Ahi*Whi + Alo*Whi + Ahi*Wlo, fp32 accum.
#define PK 72
#define TILE_HALFS (128*PK)
#define PLANE_B (TILE_HALFS*2)                // bytes per plane
#define SMEM_BYTES (4*PLANE_B + 2048)

// non-volatile: pure register dataflow, let ptxas schedule/interleave
#define MMA_BF16(c, A0,A1,A2,A3, B0,B1) \
  asm("mma.sync.aligned.m16n8k16.row.col.f32.bf16.bf16.f32 " \
    "{%0,%1,%2,%3}, {%4,%5,%6,%7}, {%8,%9}, {%0,%1,%2,%3};" \
    : "+f"((c)[0]), "+f"((c)[1]), "+f"((c)[2]), "+f"((c)[3]) \
    : "r"(A0), "r"(A1), "r"(A2), "r"(A3), "r"(B0), "r"(B1))

__global__ __launch_bounds__(256,2) void k_tgemm(
    const __nv_bfloat16* __restrict__ Ah, const __nv_bfloat16* __restrict__ Al,
    const __nv_bfloat16* __restrict__ Wh, const __nv_bfloat16* __restrict__ Wl,
    const float* __restrict__ bias, const int* __restrict__ seq,
    __nv_bfloat16* __restrict__ Ch, __nv_bfloat16* __restrict__ Cl,
    float* __restrict__ Cf, const float* __restrict__ swv, int epi)
{
  extern __shared__ __align__(16) char smraw[];
  float* t_s = (float*)(smraw + 4*PLANE_B);
  const uint32_t sbase = su32(smraw);

  const int tid = threadIdx.x;
  const int wid = tid>>5, lane = tid&31;
  const int g = lane>>2, t = lane&3;
  const int wm = wid & 1, wn = wid >> 1;
  const int m0 = blockIdx.x*128, n0 = blockIdx.y*128;

  const __nv_bfloat16* gsrc[4] = {Ah, Al, Wh, Wl};

  // ldmatrix per-lane source addresses
  const uint32_t aA = sbase + (((wm*64 + (lane&15))*PK) + ((lane>>4)<<3))*2;
  const uint32_t aB = sbase + 2*PLANE_B
      + (((wn*32 + (lane&7) + (((lane>>4)&1)<<3))*PK) + (((lane>>3)&1)<<3))*2;

  float acc[4][4][4];
  #pragma unroll
  for(int i=0;i<4;i++)
    #pragma unroll
    for(int j=0;j<4;j++)
      #pragma unroll
      for(int q=0;q<4;q++) acc[i][j][q]=0.f;

  for(int c4=0;c4<4;c4++){
    const int k0 = c4*64;
    if(c4) __syncthreads();
    #pragma unroll
    for(int u=tid; u<4096; u+=256){
      int plane = u>>10;
      int v = u & 1023;
      int r = v>>3, q = v&7;
      int row0 = (plane<2) ? m0 : n0;
      const __nv_bfloat16* src = gsrc[plane] + (size_t)(row0+r)*DD + k0 + q*8;
      uint32_t dst = sbase + (plane*TILE_HALFS + r*PK + q*8)*2;
      CP16(dst, src);
    }
    CP_COMMIT(); CP_WAIT0();
    __syncthreads();

    #pragma unroll
    for(int ks=0; ks<4; ks++){
      const uint32_t ko = ks*32;               // 16 halves = 32 bytes
      uint32_t ah[4][4], al[4][4];
      #pragma unroll
      for(int mt=0;mt<4;mt++){
        LDSM4(ah[mt], aA + mt*(16*PK*2) + ko);
        LDSM4(al[mt], aA + PLANE_B + mt*(16*PK*2) + ko);
      }
      #pragma unroll
      for(int ntp=0;ntp<2;ntp++){
        uint32_t bh[4], bl[4];
        LDSM4(bh, aB + ntp*(16*PK*2) + ko);
        LDSM4(bl, aB + PLANE_B + ntp*(16*PK*2) + ko);
        #pragma unroll
        for(int hf=0;hf<2;hf++){
          int nt = ntp*2 + hf;
          uint32_t bh0=bh[hf*2], bh1=bh[hf*2+1];
          uint32_t bl0=bl[hf*2], bl1=bl[hf*2+1];
          // term-major order: consecutive MMAs hit different accumulators
          #pragma unroll
          for(int mt=0;mt<4;mt++)
            MMA_BF16(acc[mt][nt], ah[mt][0],ah[mt][1],ah[mt][2],ah[mt][3], bh0,bh1);
          #pragma unroll
          for(int mt=0;mt<4;mt++)
            MMA_BF16(acc[mt][nt], al[mt][0],al[mt][1],al[mt][2],al[mt][3], bh0,bh1);
          #pragma unroll
          for(int mt=0;mt<4;mt++)
            MMA_BF16(acc[mt][nt], ah[mt][0],ah[mt][1],ah[mt][2],ah[mt][3], bl0,bl1);
        }
      }
    }
  }

  // ---- epilogue ----
  if(epi==0){
    #pragma unroll
    for(int mt=0;mt<4;mt++){
      int r = wm*64 + mt*16 + g;
      int row = m0 + r;
      bool p0 = (seq[row]==0), p1 = (seq[row+8]==0);
      float s0=0.f, s1=0.f;
      #pragma unroll
      for(int nt=0;nt<4;nt++){
        int col = n0 + wn*32 + nt*8 + 2*t;
        float b0v = bias[col], b1v = bias[col+1];
        float* cc = acc[mt][nt];
        float v00 = p0 ? 0.f : cc[0]+b0v;
        float v01 = p0 ? 0.f : cc[1]+b1v;
        float v10 = p1 ? 0.f : cc[2]+b0v;
        float v11 = p1 ? 0.f : cc[3]+b1v;
        float w0 = swv[col], w1 = swv[col+1];
        s0 += v00*w0 + v01*w1;
        s1 += v10*w0 + v11*w1;
        float h0 = __bfloat162float(__float2bfloat16_rn(v00));
        float h1 = __bfloat162float(__float2bfloat16_rn(v01));
        *(uint32_t*)(Ch + (size_t)row*DD + col) = bfp2(h0,h1);
        *(uint32_t*)(Cl + (size_t)row*DD + col) = bfp2(v00-h0, v01-h1);
        float h2 = __bfloat162float(__float2bfloat16_rn(v10));
        float h3 = __bfloat162float(__float2bfloat16_rn(v11));
        *(uint32_t*)(Ch + (size_t)(row+8)*DD + col) = bfp2(h2,h3);
        *(uint32_t*)(Cl + (size_t)(row+8)*DD + col) = bfp2(v10-h2, v11-h3);
      }
      s0 += __shfl_xor_sync(0xffffffffu, s0, 1);
      s0 += __shfl_xor_sync(0xffffffffu, s0, 2);
      s1 += __shfl_xor_sync(0xffffffffu, s1, 1);
      s1 += __shfl_xor_sync(0xffffffffu, s1, 2);
      if(t==0){
        t_s[wn*128 + r]     = s0;
        t_s[wn*128 + r + 8] = s1;
      }
    }
    __syncthreads();
    if(tid < 128){
      float v = t_s[tid] + t_s[128+tid] + t_s[256+tid] + t_s[384+tid];
      g_tp[blockIdx.y*MM + m0 + tid] = v;
    }
  } else {
    #pragma unroll
    for(int mt=0;mt<4;mt++){
      int row = m0 + wm*64 + mt*16 + g;
      #pragma unroll
      for(int nt=0;nt<4;nt++){
        int col = n0 + wn*32 + nt*8 + 2*t;
        float b0v = bias[col], b1v = bias[col+1];
        float* cc = acc[mt][nt];
        size_t o0off = (size_t)row*DD + col;
        size_t o1off = (size_t)(row+8)*DD + col;
        float2 zh0 = unpk(*(const uint32_t*)(Ah + o0off));
        float2 zl0 = unpk(*(const uint32_t*)(Al + o0off));
        float2 zh1 = unpk(*(const uint32_t*)(Ah + o1off));
        float2 zl1 = unpk(*(const uint32_t*)(Al + o1off));
        float2 o0 = make_float2((zh0.x+zl0.x) + fmaxf(cc[0]+b0v,0.f),
                                (zh0.y+zl0.y) + fmaxf(cc[1]+b1v,0.f));
        float2 o1 = make_float2((zh1.x+zl1.x) + fmaxf(cc[2]+b0v,0.f),
                                (zh1.y+zl1.y) + fmaxf(cc[3]+b1v,0.f));
        *(float2*)&Cf[o0off] = o0;
        *(float2*)&Cf[o1off] = o1;
      }
    }
  }
}

// ------- K_mixw: fused collapsed-softmax weights + mix, 12 rows/thread -----
__global__ __launch_bounds__(256) void k_mixw(){
  __shared__ float4 wsm[48];
  int tid = threadIdx.x;
  int cid0 = blockIdx.x*4;
  if(tid < 48){
    int s = tid;
    int cid = cid0 + s/12, j = s - (s/12)*12;
    int b = cid/NCH, c = cid - b*NCH;
    int l0 = c*12, l = l0 + j;
    int len = g_len[b];
    float4 w = make_float4(0.f,0.f,0.f,0.f);
    if(l < LL && l < len){
      const float* t0p = &g_tp[b*LL];
      const float* t1p = &g_tp[MM + b*LL];
      float tv[12];
      #pragma unroll
      for(int jj=0;jj<12;jj++){
        int p = l0 + jj;
        tv[jj] = (p < LL) ? (t0p[p] + t1p[p]) : 0.f;
      }
      int a2 = j & ~1, a3 = (j/3)*3, a4 = j & ~3;
      float s2v = tv[a2]+tv[a2+1];
      float s3v = tv[a3]+tv[a3+1]+tv[a3+2];
      float s4v = tv[a4]+tv[a4+1]+tv[a4+2]+tv[a4+3];
      float c2 = (float)(min(l0+a2+2, len) - (l0+a2));
      float c3 = (float)(min(l0+a3+3, len) - (l0+a3));
      float c4 = (float)(min(l0+a4+4, len) - (l0+a4));
      float m2 = s2v/c2, m3 = s3v/c3, m4 = s4v/c4;
      float t0 = tv[j];
      float mx = fmaxf(fmaxf(t0,m2), fmaxf(m3,m4));
      float e0=expf(t0-mx), e2=expf(m2-mx), e3=expf(m3-mx), e4=expf(m4-mx);
      float inv = 1.f/(e0 + 2.f*e2 + 3.f*e3 + 4.f*e4);
      w = make_float4(e0*inv, 2.f*e2*inv/c2, 3.f*e3*inv/c3, 4.f*e4*inv/c4);
    }
    wsm[s] = w;
  }
  __syncthreads();

  int idx = blockIdx.x*256 + tid;
  int cid = idx >> 6;
  int d4  = (idx & 63) << 2;
  int b = cid / NCH, c = cid - b*NCH;
  int l0 = c*12;
  int slot0 = (tid>>6)*12;
  size_t base = ((size_t)b*LL)*DD + d4;
  float v[12][4];
  float s2[6][4], s3[4][4];
  #pragma unroll
  for(int j=0;j<6;j++) s2[j][0]=s2[j][1]=s2[j][2]=s2[j][3]=0.f;
  #pragma unroll
  for(int j=0;j<4;j++) s3[j][0]=s3[j][1]=s3[j][2]=s3[j][3]=0.f;
  #pragma unroll
  for(int j=0;j<12;j++){
    int l = l0 + j;
    if(l < LL){
      load4(g_yh, g_yl, base + (size_t)l*DD, v[j]);
      #pragma unroll
      for(int i=0;i<4;i++){
        s2[j>>1][i] += v[j][i];
        s3[j/3][i]  += v[j][i];
      }
    } else {
      v[j][0]=v[j][1]=v[j][2]=v[j][3]=0.f;
    }
  }
  #pragma unroll
  for(int j=0;j<12;j++){
    int l = l0 + j;
    if(l < LL){
      size_t off = base + (size_t)l*DD;
      float4 w = wsm[slot0 + j];
      int q = j>>2;
      float o[4];
      #pragma unroll
      for(int i=0;i<4;i++)
        o[i] = w.x*v[j][i] + w.y*s2[j>>1][i] + w.z*s3[j/3][i]
             + w.w*(s2[2*q][i] + s2[2*q+1][i]);
      uint2 H,L; split4(o,H,L);
      *(uint2*)(g_zh+off) = H;
      *(uint2*)(g_zl+off) = L;
    }
  }
}

// ---------------- launch ----------------------------------------------------
extern "C" void kernel_launch(void* const* d_in, const int* in_sizes, int n_in,
                              void* d_out, int out_size){
  const int*   seq = (const int*)  d_in[0];
  const float* emb = (const float*)d_in[2];
  const float* cw  = (const float*)d_in[3];
  const float* cb  = (const float*)d_in[4];
  const float* pw  = (const float*)d_in[5];
  const float* pb  = (const float*)d_in[6];
  const float* sw  = (const float*)d_in[7];
  const float* fw  = (const float*)d_in[9];
  const float* fb  = (const float*)d_in[10];
  float* out = (float*)d_out;

  __nv_bfloat16 *xch,*xcl,*yh,*yl,*zh,*zl,*pwh,*pwl,*fwh,*fwl;
  cudaGetSymbolAddress((void**)&xch, g_xch);
  cudaGetSymbolAddress((void**)&xcl, g_xcl);
  cudaGetSymbolAddress((void**)&yh,  g_yh);
  cudaGetSymbolAddress((void**)&yl,  g_yl);
  cudaGetSymbolAddress((void**)&zh,  g_zh);
  cudaGetSymbolAddress((void**)&zl,  g_zl);
  cudaGetSymbolAddress((void**)&pwh, g_pwh);
  cudaGetSymbolAddress((void**)&pwl, g_pwl);
  cudaGetSymbolAddress((void**)&fwh, g_fwh);
  cudaGetSymbolAddress((void**)&fwl, g_fwl);

  cudaFuncSetAttribute(k_tgemm, cudaFuncAttributeMaxDynamicSharedMemorySize, SMEM_BYTES);

  k_prep <<<LEN_BLKS+WS_BLKS+BX_BLKS, 256>>>(seq, emb, cw, cb, pw, fw);
  k_tgemm<<<dim3(MM/128, 2), 256, SMEM_BYTES>>>(xch, xcl, pwh, pwl, pb, seq, yh, yl, nullptr, sw, 0);
  k_mixw <<<BB*NCH*64/256, 256>>>();
  k_tgemm<<<dim3(MM/128, 2), 256, SMEM_BYTES>>>(zh, zl, fwh, fwl, fb, seq, nullptr, nullptr, out, sw, 1);
}